// round 12
// baseline (speedup 1.0000x reference)
#include <cuda_runtime.h>

#define BATCH  4096
#define IDIM   1024
#define BOND   32
#define ODIM   512

// Tree: 1024 cores -> 128 (prod8) -> 16 (prod8); fork-join with scalar kernel.
#define NP1 128
#define NP2 16

__device__ __align__(16) float g_P1[NP1 * BOND * BOND];
__device__ __align__(16) float g_P2[NP2 * BOND * BOND];
__device__ __align__(16) float g_S[BATCH];

// ---------------------------------------------------------------------------
// Transposed store of a float4 covering elements 4t..4t+3 of a 32x32 matrix
// into Bt (pitch 33). Conflict-free.
// ---------------------------------------------------------------------------
__device__ __forceinline__ void transpose_store(float4 v, float* Bt, int t) {
    const int j  = t >> 3;
    const int k0 = (t & 7) * 4;
    Bt[(k0 + 0) * 33 + j] = v.x;
    Bt[(k0 + 1) * 33 + j] = v.y;
    Bt[(k0 + 2) * 33 + j] = v.z;
    Bt[(k0 + 3) * 33 + j] = v.w;
}

// ---------------------------------------------------------------------------
// Block = ordered product of 8 consecutive 32x32 matrices (depth 7).
// ---------------------------------------------------------------------------
__global__ __launch_bounds__(256) void mps_prod8_kernel(const float* __restrict__ src,
                                                        float* __restrict__ dst) {
    __shared__ float sA[BOND * BOND];
    __shared__ float sBt[2][BOND * 33];

    const int t    = threadIdx.x;
    const int w    = t >> 5;
    const int lane = t & 31;
    const float* base = src + (size_t)blockIdx.x * (8 * BOND * BOND);

    ((float4*)sA)[t] = ((const float4*)base)[t];
    transpose_store(((const float4*)(base + BOND * BOND))[t], sBt[1], t);
    __syncthreads();

    float acc0 = 0.f, acc1 = 0.f, acc2 = 0.f, acc3 = 0.f;

    #pragma unroll
    for (int s = 1; s < 8; ++s) {
        float4 pre;
        if (s + 1 < 8) pre = ((const float4*)(base + (s + 1) * BOND * BOND))[t];

        const float* Bt = sBt[s & 1];
        acc0 = acc1 = acc2 = acc3 = 0.f;

        #pragma unroll
        for (int l4 = 0; l4 < 8; ++l4) {
            const float4 a0 = *(const float4*)(sA + (4 * w + 0) * 32 + 4 * l4);
            const float4 a1 = *(const float4*)(sA + (4 * w + 1) * 32 + 4 * l4);
            const float4 a2 = *(const float4*)(sA + (4 * w + 2) * 32 + 4 * l4);
            const float4 a3 = *(const float4*)(sA + (4 * w + 3) * 32 + 4 * l4);
            const float b0 = Bt[lane * 33 + 4 * l4 + 0];
            const float b1 = Bt[lane * 33 + 4 * l4 + 1];
            const float b2 = Bt[lane * 33 + 4 * l4 + 2];
            const float b3 = Bt[lane * 33 + 4 * l4 + 3];

            acc0 = fmaf(a0.x, b0, acc0); acc0 = fmaf(a0.y, b1, acc0);
            acc0 = fmaf(a0.z, b2, acc0); acc0 = fmaf(a0.w, b3, acc0);
            acc1 = fmaf(a1.x, b0, acc1); acc1 = fmaf(a1.y, b1, acc1);
            acc1 = fmaf(a1.z, b2, acc1); acc1 = fmaf(a1.w, b3, acc1);
            acc2 = fmaf(a2.x, b0, acc2); acc2 = fmaf(a2.y, b1, acc2);
            acc2 = fmaf(a2.z, b2, acc2); acc2 = fmaf(a2.w, b3, acc2);
            acc3 = fmaf(a3.x, b0, acc3); acc3 = fmaf(a3.y, b1, acc3);
            acc3 = fmaf(a3.z, b2, acc3); acc3 = fmaf(a3.w, b3, acc3);
        }
        __syncthreads();
        if (s < 7) {
            sA[(4 * w + 0) * 32 + lane] = acc0;
            sA[(4 * w + 1) * 32 + lane] = acc1;
            sA[(4 * w + 2) * 32 + lane] = acc2;
            sA[(4 * w + 3) * 32 + lane] = acc3;
            transpose_store(pre, sBt[(s + 1) & 1], t);
            __syncthreads();
        }
    }

    float* d = dst + (size_t)blockIdx.x * (BOND * BOND);
    d[(4 * w + 0) * 32 + lane] = acc0;
    d[(4 * w + 1) * 32 + lane] = acc1;
    d[(4 * w + 2) * 32 + lane] = acc2;
    d[(4 * w + 3) * 32 + lane] = acc3;
}

// ---------------------------------------------------------------------------
// Kernel A: per-row scalar products. One warp per row, 8 rows per block,
// no smem / no barriers, 8 independent LDG.128 per lane. Writes g_S[b].
// Runs CONCURRENTLY with the tree branch (independent inputs).
// ---------------------------------------------------------------------------
__global__ __launch_bounds__(256) void mps_scal_kernel(const float* __restrict__ inputs,
                                                       float* __restrict__ S) {
    const int lane = threadIdx.x & 31;
    const int b    = blockIdx.x * 8 + (threadIdx.x >> 5);

    const float4* row = (const float4*)(inputs + (size_t)b * IDIM);
    float4 r[8];
    #pragma unroll
    for (int i = 0; i < 8; ++i) r[i] = row[lane + 32 * i];

    float p0 = (r[0].x * r[0].y) * (r[0].z * r[0].w);
    float p1 = (r[1].x * r[1].y) * (r[1].z * r[1].w);
    float p2 = (r[2].x * r[2].y) * (r[2].z * r[2].w);
    float p3 = (r[3].x * r[3].y) * (r[3].z * r[3].w);
    float p4 = (r[4].x * r[4].y) * (r[4].z * r[4].w);
    float p5 = (r[5].x * r[5].y) * (r[5].z * r[5].w);
    float p6 = (r[6].x * r[6].y) * (r[6].z * r[6].w);
    float p7 = (r[7].x * r[7].y) * (r[7].z * r[7].w);
    float p  = ((p0 * p1) * (p2 * p3)) * ((p4 * p5) * (p6 * p7));

    #pragma unroll
    for (int off = 16; off; off >>= 1)
        p *= __shfl_xor_sync(0xffffffffu, p, off);

    if (lane == 0) S[b] = p;
}

// ---------------------------------------------------------------------------
// Kernel C (join): 128 blocks x 1024 threads, 32 rows/block. Stages the 16
// P2 matrices (64KB smem), warp 0 runs the 16-step chain, 512 threads do
// w = v @ proj once per block, then all warps write out = s*w + bias.
// ---------------------------------------------------------------------------
#define SMEM_FLOATS (NP2 * 1024 + ODIM + BOND)

__global__ __launch_bounds__(1024) void mps_out_kernel(
        const float* __restrict__ proj,
        const float* __restrict__ bias,
        const float* __restrict__ S,
        float* __restrict__ out) {
    extern __shared__ float sP[];
    float* sw = sP + NP2 * 1024;
    float* sv = sw + ODIM;

    const int tid  = threadIdx.x;
    const int wid  = tid >> 5;
    const int lane = tid & 31;
    const int b    = blockIdx.x * 32 + wid;

    const float s = S[b];                  // uniform per warp (broadcast LDG)

    // stage P2: 1024 threads * 4 float4 = 64KB
    {
        const float4* g4 = (const float4*)g_P2;
        float4*       s4 = (float4*)sP;
        #pragma unroll
        for (int i = 0; i < 4; ++i) s4[tid + 1024 * i] = g4[tid + 1024 * i];
    }
    __syncthreads();

    if (wid == 0) {
        float v = 1.0f;
        #pragma unroll
        for (int c = 0; c < NP2; ++c) {
            const float* P = sP + c * 1024;
            float a0 = 0.f, a1 = 0.f, a2 = 0.f, a3 = 0.f;
            #pragma unroll
            for (int j = 0; j < 8; ++j) {
                a0 = fmaf(__shfl_sync(0xffffffffu, v, j),      P[j * 32 + lane],        a0);
                a1 = fmaf(__shfl_sync(0xffffffffu, v, j + 8),  P[(j + 8) * 32 + lane],  a1);
                a2 = fmaf(__shfl_sync(0xffffffffu, v, j + 16), P[(j + 16) * 32 + lane], a2);
                a3 = fmaf(__shfl_sync(0xffffffffu, v, j + 24), P[(j + 24) * 32 + lane], a3);
            }
            v = (a0 + a1) + (a2 + a3);
        }
        sv[lane] = v;
    }
    __syncthreads();

    if (tid < ODIM) {
        float a0 = 0.f, a1 = 0.f, a2 = 0.f, a3 = 0.f;
        #pragma unroll
        for (int j = 0; j < 8; ++j) {
            a0 = fmaf(sv[j],      proj[(j)      * ODIM + tid], a0);
            a1 = fmaf(sv[j + 8],  proj[(j + 8)  * ODIM + tid], a1);
            a2 = fmaf(sv[j + 16], proj[(j + 16) * ODIM + tid], a2);
            a3 = fmaf(sv[j + 24], proj[(j + 24) * ODIM + tid], a3);
        }
        sw[tid] = (a0 + a1) + (a2 + a3);
    }
    __syncthreads();

    const float4* w4 = (const float4*)sw;
    const float4* b4 = (const float4*)bias;
    float4*       o4 = (float4*)(out + (size_t)b * ODIM);
    #pragma unroll
    for (int i = 0; i < 4; ++i) {
        const float4 wv = w4[lane + 32 * i];
        const float4 bv = b4[lane + 32 * i];
        float4 ov;
        ov.x = fmaf(s, wv.x, bv.x);
        ov.y = fmaf(s, wv.y, bv.y);
        ov.z = fmaf(s, wv.z, bv.z);
        ov.w = fmaf(s, wv.w, bv.w);
        o4[lane + 32 * i] = ov;
    }
}

// ---------------------------------------------------------------------------
// Fork-join capture: scalars kernel (legacy stream) runs concurrently with
// the two tree kernels (side stream); event join before the output kernel.
// Streams/events are host-side objects (no device memory); created per call
// and leaked (kernel_launch runs only a handful of times).
// ---------------------------------------------------------------------------
extern "C" void kernel_launch(void* const* d_in, const int* in_sizes, int n_in,
                              void* d_out, int out_size) {
    const float* inputs = (const float*)d_in[0];
    const float* cores  = (const float*)d_in[1];
    const float* proj   = (const float*)d_in[2];
    const float* bias   = (const float*)d_in[3];
    float* out = (float*)d_out;

    float* p1; cudaGetSymbolAddress((void**)&p1, g_P1);
    float* p2; cudaGetSymbolAddress((void**)&p2, g_P2);
    float* sS; cudaGetSymbolAddress((void**)&sS, g_S);

    cudaFuncSetAttribute(mps_out_kernel,
                         cudaFuncAttributeMaxDynamicSharedMemorySize,
                         SMEM_FLOATS * (int)sizeof(float));

    cudaStream_t s2;
    cudaEvent_t  e0, e1;
    cudaStreamCreateWithFlags(&s2, cudaStreamNonBlocking);
    cudaEventCreateWithFlags(&e0, cudaEventDisableTiming);
    cudaEventCreateWithFlags(&e1, cudaEventDisableTiming);

    // fork: side stream joins the capture via event dependency
    cudaEventRecord(e0, 0);
    cudaStreamWaitEvent(s2, e0, 0);

    // branch 1 (legacy stream): input scalars, 16MB read
    mps_scal_kernel<<<BATCH / 8, 256>>>(inputs, sS);

    // branch 2 (side stream): core tree
    mps_prod8_kernel<<<NP1, 256, 0, s2>>>(cores, p1);   // 1024 -> 128
    mps_prod8_kernel<<<NP2, 256, 0, s2>>>(p1, p2);      // 128  -> 16

    // join
    cudaEventRecord(e1, s2);
    cudaStreamWaitEvent(0, e1, 0);

    mps_out_kernel<<<BATCH / 32, 1024, SMEM_FLOATS * sizeof(float)>>>(
        proj, bias, sS, out);
}

// round 13
// speedup vs baseline: 1.0226x; 1.0226x over previous
#include <cuda_runtime.h>

#define BATCH  4096
#define IDIM   1024
#define BOND   32
#define ODIM   512
#define GRID   128

// Tree inside one persistent kernel: 1024 cores -> 128 -> 16 -> chain.
#define NP1 128
#define NP2 16

__device__ __align__(16) float g_P1[NP1 * BOND * BOND];
__device__ __align__(16) float g_P2[NP2 * BOND * BOND];
__device__ __align__(16) float g_w[ODIM];
__device__ unsigned g_bar_cnt = 0;   // monotonic ticket barrier (replay-safe)

// ---------------------------------------------------------------------------
// Grid-wide barrier: monotonic ticket counter, generation = ticket/GRID.
// Deterministic, no reset needed across graph replays.
// ---------------------------------------------------------------------------
__device__ __forceinline__ void grid_sync() {
    __syncthreads();
    if (threadIdx.x == 0) {
        __threadfence();
        unsigned ticket = atomicAdd(&g_bar_cnt, 1u);
        unsigned target = (ticket / GRID + 1u) * GRID;
        volatile unsigned* p = &g_bar_cnt;
        while (*p < target) { }
    }
    __syncthreads();
}

// 256-thread named barrier (warps 0..7 only)
#define BAR256() asm volatile("bar.sync 1, 256;" ::: "memory")

// ---------------------------------------------------------------------------
// Transposed store of a float4 covering elements 4t..4t+3 of a 32x32 matrix
// into Bt (pitch 33). Conflict-free.
// ---------------------------------------------------------------------------
__device__ __forceinline__ void transpose_store(float4 v, float* Bt, int t) {
    const int j  = t >> 3;
    const int k0 = (t & 7) * 4;
    Bt[(k0 + 0) * 33 + j] = v.x;
    Bt[(k0 + 1) * 33 + j] = v.y;
    Bt[(k0 + 2) * 33 + j] = v.z;
    Bt[(k0 + 3) * 33 + j] = v.w;
}

// ---------------------------------------------------------------------------
// Ordered product of 8 consecutive 32x32 matrices, executed by threads
// t = 0..255 (warps 0..7) using the named 256-thread barrier.
// Warp w owns rows 4w..4w+3; lane = output column.
// ---------------------------------------------------------------------------
__device__ void prod8_256(const float* __restrict__ base, float* __restrict__ dst,
                          float* sA, float* sBt2, int t) {
    const int w    = t >> 5;
    const int lane = t & 31;

    ((float4*)sA)[t] = ((const float4*)base)[t];
    transpose_store(((const float4*)(base + BOND * BOND))[t], sBt2 + 1056, t);
    BAR256();

    float acc0 = 0.f, acc1 = 0.f, acc2 = 0.f, acc3 = 0.f;

    #pragma unroll
    for (int s = 1; s < 8; ++s) {
        float4 pre;
        if (s + 1 < 8) pre = ((const float4*)(base + (s + 1) * BOND * BOND))[t];

        const float* Bt = sBt2 + (s & 1) * 1056;
        acc0 = acc1 = acc2 = acc3 = 0.f;

        #pragma unroll
        for (int l4 = 0; l4 < 8; ++l4) {
            const float4 a0 = *(const float4*)(sA + (4 * w + 0) * 32 + 4 * l4);
            const float4 a1 = *(const float4*)(sA + (4 * w + 1) * 32 + 4 * l4);
            const float4 a2 = *(const float4*)(sA + (4 * w + 2) * 32 + 4 * l4);
            const float4 a3 = *(const float4*)(sA + (4 * w + 3) * 32 + 4 * l4);
            const float b0 = Bt[lane * 33 + 4 * l4 + 0];
            const float b1 = Bt[lane * 33 + 4 * l4 + 1];
            const float b2 = Bt[lane * 33 + 4 * l4 + 2];
            const float b3 = Bt[lane * 33 + 4 * l4 + 3];

            acc0 = fmaf(a0.x, b0, acc0); acc0 = fmaf(a0.y, b1, acc0);
            acc0 = fmaf(a0.z, b2, acc0); acc0 = fmaf(a0.w, b3, acc0);
            acc1 = fmaf(a1.x, b0, acc1); acc1 = fmaf(a1.y, b1, acc1);
            acc1 = fmaf(a1.z, b2, acc1); acc1 = fmaf(a1.w, b3, acc1);
            acc2 = fmaf(a2.x, b0, acc2); acc2 = fmaf(a2.y, b1, acc2);
            acc2 = fmaf(a2.z, b2, acc2); acc2 = fmaf(a2.w, b3, acc2);
            acc3 = fmaf(a3.x, b0, acc3); acc3 = fmaf(a3.y, b1, acc3);
            acc3 = fmaf(a3.z, b2, acc3); acc3 = fmaf(a3.w, b3, acc3);
        }
        BAR256();
        if (s < 7) {
            sA[(4 * w + 0) * 32 + lane] = acc0;
            sA[(4 * w + 1) * 32 + lane] = acc1;
            sA[(4 * w + 2) * 32 + lane] = acc2;
            sA[(4 * w + 3) * 32 + lane] = acc3;
            transpose_store(pre, sBt2 + ((s + 1) & 1) * 1056, t);
            BAR256();
        }
    }

    d:
    dst[(4 * w + 0) * 32 + lane] = acc0;
    dst[(4 * w + 1) * 32 + lane] = acc1;
    dst[(4 * w + 2) * 32 + lane] = acc2;
    dst[(4 * w + 3) * 32 + lane] = acc3;
}

// ---------------------------------------------------------------------------
// Single persistent kernel. 128 blocks x 1024 threads, all co-resident.
//   P1: scalars for 32 rows/block (s kept in registers) + prod8 level 1
//   P2: blocks 0..15 prod8 level 2
//   P3: block 0: stage P2 -> smem, chain, projection -> g_w
//   P4: all blocks write out = s*w + bias
// dynamic smem: sP[16*1024] floats (64KB), used by block 0 in P3 only.
// ---------------------------------------------------------------------------
__global__ __launch_bounds__(1024, 1) void mps_mono_kernel(
        const float* __restrict__ inputs,
        const float* __restrict__ cores,
        const float* __restrict__ proj,
        const float* __restrict__ bias,
        float* __restrict__ out) {
    extern __shared__ float sP[];                 // 64KB (block 0, phase 3)
    __shared__ float sA[BOND * BOND];             // prod8 running product
    __shared__ float sBt2[2 * 1056];              // prod8 transposed buffers
    __shared__ float sv[BOND];
    __shared__ float sw[ODIM];

    const int tid  = threadIdx.x;
    const int wid  = tid >> 5;
    const int lane = tid & 31;
    const int blk  = blockIdx.x;
    const int b    = blk * 32 + wid;              // this warp's batch row

    // ---- Phase 1a: per-row scalar product (all 32 warps) ----
    const float4* row = (const float4*)(inputs + (size_t)b * IDIM);
    float4 r[8];
    #pragma unroll
    for (int i = 0; i < 8; ++i) r[i] = row[lane + 32 * i];

    float p0 = (r[0].x * r[0].y) * (r[0].z * r[0].w);
    float p1 = (r[1].x * r[1].y) * (r[1].z * r[1].w);
    float p2 = (r[2].x * r[2].y) * (r[2].z * r[2].w);
    float p3 = (r[3].x * r[3].y) * (r[3].z * r[3].w);
    float p4 = (r[4].x * r[4].y) * (r[4].z * r[4].w);
    float p5 = (r[5].x * r[5].y) * (r[5].z * r[5].w);
    float p6 = (r[6].x * r[6].y) * (r[6].z * r[6].w);
    float p7 = (r[7].x * r[7].y) * (r[7].z * r[7].w);
    float s  = ((p0 * p1) * (p2 * p3)) * ((p4 * p5) * (p6 * p7));
    #pragma unroll
    for (int off = 16; off; off >>= 1)
        s *= __shfl_xor_sync(0xffffffffu, s, off);
    // s is lane-uniform and lives in a register until phase 4.

    // ---- Phase 1b: prod8 level 1 (warps 0..7) ----
    if (tid < 256)
        prod8_256(cores + (size_t)blk * 8 * BOND * BOND,
                  g_P1 + (size_t)blk * BOND * BOND, sA, sBt2, tid);

    grid_sync();

    // ---- Phase 2: prod8 level 2 (blocks 0..15, warps 0..7) ----
    if (blk < NP2 && tid < 256)
        prod8_256(g_P1 + (size_t)blk * 8 * BOND * BOND,
                  g_P2 + (size_t)blk * BOND * BOND, sA, sBt2, tid);

    grid_sync();

    // ---- Phase 3: block 0 computes w = (ones @ P2 chain) @ proj ----
    if (blk == 0) {
        {   // stage P2: 1024 threads * 4 float4 = 64KB
            const float4* g4 = (const float4*)g_P2;
            float4*       s4 = (float4*)sP;
            #pragma unroll
            for (int i = 0; i < 4; ++i) s4[tid + 1024 * i] = g4[tid + 1024 * i];
        }
        __syncthreads();

        if (wid == 0) {
            float v = 1.0f;
            #pragma unroll
            for (int c = 0; c < NP2; ++c) {
                const float* P = sP + c * 1024;
                float a0 = 0.f, a1 = 0.f, a2 = 0.f, a3 = 0.f;
                #pragma unroll
                for (int j = 0; j < 8; ++j) {
                    a0 = fmaf(__shfl_sync(0xffffffffu, v, j),      P[j * 32 + lane],        a0);
                    a1 = fmaf(__shfl_sync(0xffffffffu, v, j + 8),  P[(j + 8) * 32 + lane],  a1);
                    a2 = fmaf(__shfl_sync(0xffffffffu, v, j + 16), P[(j + 16) * 32 + lane], a2);
                    a3 = fmaf(__shfl_sync(0xffffffffu, v, j + 24), P[(j + 24) * 32 + lane], a3);
                }
                v = (a0 + a1) + (a2 + a3);
            }
            sv[lane] = v;
        }
        __syncthreads();

        if (tid < ODIM) {
            float a0 = 0.f, a1 = 0.f, a2 = 0.f, a3 = 0.f;
            #pragma unroll
            for (int j = 0; j < 8; ++j) {
                a0 = fmaf(sv[j],      proj[(j)      * ODIM + tid], a0);
                a1 = fmaf(sv[j + 8],  proj[(j + 8)  * ODIM + tid], a1);
                a2 = fmaf(sv[j + 16], proj[(j + 16) * ODIM + tid], a2);
                a3 = fmaf(sv[j + 24], proj[(j + 24) * ODIM + tid], a3);
            }
            g_w[tid] = (a0 + a1) + (a2 + a3);
        }
    }

    grid_sync();

    // ---- Phase 4: out[b,:] = s * w + bias (all blocks) ----
    {   // stage w once per block into smem (coalesced, then broadcast reads)
        if (tid < 128) ((float4*)sw)[tid] = ((const float4*)g_w)[tid];
        __syncthreads();
    }

    const float4* w4 = (const float4*)sw;
    const float4* b4 = (const float4*)bias;
    float4*       o4 = (float4*)(out + (size_t)b * ODIM);
    #pragma unroll
    for (int i = 0; i < 4; ++i) {
        const float4 wv = w4[lane + 32 * i];
        const float4 bv = b4[lane + 32 * i];
        float4 ov;
        ov.x = fmaf(s, wv.x, bv.x);
        ov.y = fmaf(s, wv.y, bv.y);
        ov.z = fmaf(s, wv.z, bv.z);
        ov.w = fmaf(s, wv.w, bv.w);
        o4[lane + 32 * i] = ov;
    }
}

// ---------------------------------------------------------------------------
extern "C" void kernel_launch(void* const* d_in, const int* in_sizes, int n_in,
                              void* d_out, int out_size) {
    const float* inputs = (const float*)d_in[0];
    const float* cores  = (const float*)d_in[1];
    const float* proj   = (const float*)d_in[2];
    const float* bias   = (const float*)d_in[3];
    float* out = (float*)d_out;

    cudaFuncSetAttribute(mps_mono_kernel,
                         cudaFuncAttributeMaxDynamicSharedMemorySize, 65536);

    mps_mono_kernel<<<GRID, 1024, 65536>>>(inputs, cores, proj, bias, out);
}

// round 14
// speedup vs baseline: 1.0370x; 1.0140x over previous
#include <cuda_runtime.h>

#define BATCH  4096
#define IDIM   1024
#define BOND   32
#define ODIM   512

#define NP1 128    // level-1 products (1024 cores -> 128)
#define NP2 16     // level-2 products (128 -> 16)

__device__ __align__(16) float g_P1[NP1 * BOND * BOND];
__device__ __align__(16) float g_P2[NP2 * BOND * BOND];
__device__ __align__(16) float g_S[BATCH];
__device__ __align__(16) float g_w[ODIM];
__device__ unsigned g_tick = 0;     // monotonic; (t+1)%NP2==0 selects last arrival per replay

// ---------------------------------------------------------------------------
// Transposed store of a float4 covering elements 4t..4t+3 of a 32x32 matrix
// into Bt (pitch 33). Conflict-free.
// ---------------------------------------------------------------------------
__device__ __forceinline__ void transpose_store(float4 v, float* Bt, int t) {
    const int j  = t >> 3;
    const int k0 = (t & 7) * 4;
    Bt[(k0 + 0) * 33 + j] = v.x;
    Bt[(k0 + 1) * 33 + j] = v.y;
    Bt[(k0 + 2) * 33 + j] = v.z;
    Bt[(k0 + 3) * 33 + j] = v.w;
}

// ---------------------------------------------------------------------------
// Ordered product of 8 consecutive 32x32 matrices; full 256-thread block.
// Warp w owns rows 4w..4w+3; lane = output column. A rows broadcast LDS.128.
// ---------------------------------------------------------------------------
__device__ void prod8_block(const float* __restrict__ base, float* __restrict__ dst,
                            float* sA, float* sBt2) {
    const int t    = threadIdx.x;
    const int w    = t >> 5;
    const int lane = t & 31;

    ((float4*)sA)[t] = ((const float4*)base)[t];
    transpose_store(((const float4*)(base + BOND * BOND))[t], sBt2 + 1056, t);
    __syncthreads();

    float acc0 = 0.f, acc1 = 0.f, acc2 = 0.f, acc3 = 0.f;

    #pragma unroll
    for (int s = 1; s < 8; ++s) {
        float4 pre;
        if (s + 1 < 8) pre = ((const float4*)(base + (s + 1) * BOND * BOND))[t];

        const float* Bt = sBt2 + (s & 1) * 1056;
        acc0 = acc1 = acc2 = acc3 = 0.f;

        #pragma unroll
        for (int l4 = 0; l4 < 8; ++l4) {
            const float4 a0 = *(const float4*)(sA + (4 * w + 0) * 32 + 4 * l4);
            const float4 a1 = *(const float4*)(sA + (4 * w + 1) * 32 + 4 * l4);
            const float4 a2 = *(const float4*)(sA + (4 * w + 2) * 32 + 4 * l4);
            const float4 a3 = *(const float4*)(sA + (4 * w + 3) * 32 + 4 * l4);
            const float b0 = Bt[lane * 33 + 4 * l4 + 0];
            const float b1 = Bt[lane * 33 + 4 * l4 + 1];
            const float b2 = Bt[lane * 33 + 4 * l4 + 2];
            const float b3 = Bt[lane * 33 + 4 * l4 + 3];

            acc0 = fmaf(a0.x, b0, acc0); acc0 = fmaf(a0.y, b1, acc0);
            acc0 = fmaf(a0.z, b2, acc0); acc0 = fmaf(a0.w, b3, acc0);
            acc1 = fmaf(a1.x, b0, acc1); acc1 = fmaf(a1.y, b1, acc1);
            acc1 = fmaf(a1.z, b2, acc1); acc1 = fmaf(a1.w, b3, acc1);
            acc2 = fmaf(a2.x, b0, acc2); acc2 = fmaf(a2.y, b1, acc2);
            acc2 = fmaf(a2.z, b2, acc2); acc2 = fmaf(a2.w, b3, acc2);
            acc3 = fmaf(a3.x, b0, acc3); acc3 = fmaf(a3.y, b1, acc3);
            acc3 = fmaf(a3.z, b2, acc3); acc3 = fmaf(a3.w, b3, acc3);
        }
        __syncthreads();
        if (s < 7) {
            sA[(4 * w + 0) * 32 + lane] = acc0;
            sA[(4 * w + 1) * 32 + lane] = acc1;
            sA[(4 * w + 2) * 32 + lane] = acc2;
            sA[(4 * w + 3) * 32 + lane] = acc3;
            transpose_store(pre, sBt2 + ((s + 1) & 1) * 1056, t);
            __syncthreads();
        }
    }

    dst[(4 * w + 0) * 32 + lane] = acc0;
    dst[(4 * w + 1) * 32 + lane] = acc1;
    dst[(4 * w + 2) * 32 + lane] = acc2;
    dst[(4 * w + 3) * 32 + lane] = acc3;
}

// ---------------------------------------------------------------------------
// K1: heterogeneous grid of 640 blocks x 256 threads.
//   blocks 0..127   : tree level 1 (prod8 of cores chunk)
//   blocks 128..639 : per-row scalar products, 8 rows/block (one warp/row)
// The two roles touch disjoint data -> run concurrently, no sync needed.
// ---------------------------------------------------------------------------
__global__ __launch_bounds__(256) void mps_k1(const float* __restrict__ cores,
                                              const float* __restrict__ inputs) {
    __shared__ float sA[BOND * BOND];
    __shared__ float sBt2[2 * 1056];

    const int blk = blockIdx.x;

    if (blk < NP1) {
        prod8_block(cores + (size_t)blk * 8 * BOND * BOND,
                    g_P1 + (size_t)blk * BOND * BOND, sA, sBt2);
        return;
    }

    // scalar role
    const int lane = threadIdx.x & 31;
    const int b    = (blk - NP1) * 8 + (threadIdx.x >> 5);

    const float4* row = (const float4*)(inputs + (size_t)b * IDIM);
    float4 r[8];
    #pragma unroll
    for (int i = 0; i < 8; ++i) r[i] = row[lane + 32 * i];

    float p0 = (r[0].x * r[0].y) * (r[0].z * r[0].w);
    float p1 = (r[1].x * r[1].y) * (r[1].z * r[1].w);
    float p2 = (r[2].x * r[2].y) * (r[2].z * r[2].w);
    float p3 = (r[3].x * r[3].y) * (r[3].z * r[3].w);
    float p4 = (r[4].x * r[4].y) * (r[4].z * r[4].w);
    float p5 = (r[5].x * r[5].y) * (r[5].z * r[5].w);
    float p6 = (r[6].x * r[6].y) * (r[6].z * r[6].w);
    float p7 = (r[7].x * r[7].y) * (r[7].z * r[7].w);
    float p  = ((p0 * p1) * (p2 * p3)) * ((p4 * p5) * (p6 * p7));

    #pragma unroll
    for (int off = 16; off; off >>= 1)
        p *= __shfl_xor_sync(0xffffffffu, p, off);

    if (lane == 0) g_S[b] = p;
}

// ---------------------------------------------------------------------------
// K2: 16 blocks x 256 threads. Each block: tree level 2 (prod8 of P1 chunk)
// -> g_P2. The LAST block to finish (monotonic ticket, replay-safe) then
// stages all 16 P2 matrices into 64KB dynamic smem, warp 0 runs the 16-step
// vector chain, and 256 threads compute w = v @ proj (2 outputs each).
// ---------------------------------------------------------------------------
__global__ __launch_bounds__(256) void mps_k2(const float* __restrict__ proj) {
    extern __shared__ float sP[];            // 64KB, used by last block only
    __shared__ float sA[BOND * BOND];
    __shared__ float sBt2[2 * 1056];
    __shared__ float sv[BOND];
    __shared__ unsigned sLast;

    const int tid  = threadIdx.x;
    const int lane = tid & 31;
    const int blk  = blockIdx.x;

    prod8_block(g_P1 + (size_t)blk * 8 * BOND * BOND,
                g_P2 + (size_t)blk * BOND * BOND, sA, sBt2);

    __threadfence();                          // publish g_P2[blk] (release)
    __syncthreads();
    if (tid == 0) {
        unsigned t = atomicAdd(&g_tick, 1u);
        sLast = ((t + 1u) % NP2 == 0u) ? 1u : 0u;
    }
    __syncthreads();
    if (!sLast) return;

    __threadfence();                          // acquire side

    // stage P2: 256 threads * 16 float4 = 4096 float4 = 64KB (L2 reads)
    {
        const float4* g4 = (const float4*)g_P2;
        float4*       s4 = (float4*)sP;
        #pragma unroll
        for (int i = 0; i < 16; ++i) {
            float4 v = __ldcg(g4 + tid + 256 * i);   // bypass L1 (cross-block data)
            s4[tid + 256 * i] = v;
        }
    }
    __syncthreads();

    if (tid < 32) {
        float v = 1.0f;
        #pragma unroll
        for (int c = 0; c < NP2; ++c) {
            const float* P = sP + c * 1024;
            float a0 = 0.f, a1 = 0.f, a2 = 0.f, a3 = 0.f;
            #pragma unroll
            for (int j = 0; j < 8; ++j) {
                a0 = fmaf(__shfl_sync(0xffffffffu, v, j),      P[j * 32 + lane],        a0);
                a1 = fmaf(__shfl_sync(0xffffffffu, v, j + 8),  P[(j + 8) * 32 + lane],  a1);
                a2 = fmaf(__shfl_sync(0xffffffffu, v, j + 16), P[(j + 16) * 32 + lane], a2);
                a3 = fmaf(__shfl_sync(0xffffffffu, v, j + 24), P[(j + 24) * 32 + lane], a3);
            }
            v = (a0 + a1) + (a2 + a3);
        }
        sv[lane] = v;
    }
    __syncthreads();

    // w = v @ proj : 256 threads x 2 outputs
    #pragma unroll
    for (int r = 0; r < 2; ++r) {
        const int o = tid + 256 * r;
        float a0 = 0.f, a1 = 0.f, a2 = 0.f, a3 = 0.f;
        #pragma unroll
        for (int j = 0; j < 8; ++j) {
            a0 = fmaf(sv[j],      proj[(j)      * ODIM + o], a0);
            a1 = fmaf(sv[j + 8],  proj[(j + 8)  * ODIM + o], a1);
            a2 = fmaf(sv[j + 16], proj[(j + 16) * ODIM + o], a2);
            a3 = fmaf(sv[j + 24], proj[(j + 24) * ODIM + o], a3);
        }
        g_w[o] = (a0 + a1) + (a2 + a3);
    }
}

// ---------------------------------------------------------------------------
// K3: output. 512 blocks x 256 threads, one warp per batch row.
// out[b,:] = g_S[b] * g_w + bias. Pure streaming write.
// ---------------------------------------------------------------------------
__global__ __launch_bounds__(256) void mps_k3(const float* __restrict__ bias,
                                              float* __restrict__ out) {
    const int lane = threadIdx.x & 31;
    const int b    = blockIdx.x * 8 + (threadIdx.x >> 5);

    const float s = g_S[b];                  // warp-uniform broadcast load

    const float4* w4 = (const float4*)g_w;
    const float4* b4 = (const float4*)bias;
    float4*       o4 = (float4*)(out + (size_t)b * ODIM);

    #pragma unroll
    for (int i = 0; i < 4; ++i) {
        const float4 wv = w4[lane + 32 * i];
        const float4 bv = b4[lane + 32 * i];
        float4 ov;
        ov.x = fmaf(s, wv.x, bv.x);
        ov.y = fmaf(s, wv.y, bv.y);
        ov.z = fmaf(s, wv.z, bv.z);
        ov.w = fmaf(s, wv.w, bv.w);
        o4[lane + 32 * i] = ov;
    }
}

// ---------------------------------------------------------------------------
extern "C" void kernel_launch(void* const* d_in, const int* in_sizes, int n_in,
                              void* d_out, int out_size) {
    const float* inputs = (const float*)d_in[0];
    const float* cores  = (const float*)d_in[1];
    const float* proj   = (const float*)d_in[2];
    const float* bias   = (const float*)d_in[3];
    float* out = (float*)d_out;

    cudaFuncSetAttribute(mps_k2,
                         cudaFuncAttributeMaxDynamicSharedMemorySize, 65536);

    mps_k1<<<NP1 + BATCH / 8, 256>>>(cores, inputs);   // tree L1 || scalars
    mps_k2<<<NP2, 256, 65536>>>(proj);                 // tree L2 + last-block combine
    mps_k3<<<BATCH / 8, 256>>>(bias, out);             // output stream
}

// round 15
// speedup vs baseline: 1.1168x; 1.0769x over previous
#include <cuda_runtime.h>

#define BATCH  4096
#define IDIM   1024
#define BOND   32
#define ODIM   512

// Tree: 1024 cores -> 128 (prod8) -> 16 (prod8), then fused chain+output.
#define NP1 128
#define NP2 16

__device__ __align__(16) float g_P1[NP1 * BOND * BOND];
__device__ __align__(16) float g_P2[NP2 * BOND * BOND];

// ---------------------------------------------------------------------------
// Transposed store of a float4 covering elements 4t..4t+3 of a 32x32 matrix
// into Bt (pitch 33). Conflict-free.
// ---------------------------------------------------------------------------
__device__ __forceinline__ void transpose_store(float4 v, float* Bt, int t) {
    const int j  = t >> 3;
    const int k0 = (t & 7) * 4;
    Bt[(k0 + 0) * 33 + j] = v.x;
    Bt[(k0 + 1) * 33 + j] = v.y;
    Bt[(k0 + 2) * 33 + j] = v.z;
    Bt[(k0 + 3) * 33 + j] = v.w;
}

// ---------------------------------------------------------------------------
// Ordered product of 8 consecutive 32x32 matrices (depth 7).
// ALL 8 matrices are loaded upfront into registers (8 coalesced float4 per
// thread, MLP=8 -> one memory round-trip even when cold), so the 7 serial
// matmul steps run entirely from registers/smem with no exposed load latency.
// Warp w owns rows 4w..4w+3; lane = output column.
// ---------------------------------------------------------------------------
__global__ __launch_bounds__(256) void mps_prod8_kernel(const float* __restrict__ src,
                                                        float* __restrict__ dst) {
    __shared__ float sA[BOND * BOND];
    __shared__ float sBt[2][BOND * 33];

    const int t    = threadIdx.x;
    const int w    = t >> 5;
    const int lane = t & 31;
    const float4* base4 = (const float4*)(src + (size_t)blockIdx.x * (8 * BOND * BOND));

    // upfront load: element t of each of the 8 matrices (256 float4 each)
    float4 r[8];
    #pragma unroll
    for (int i = 0; i < 8; ++i) r[i] = base4[256 * i + t];

    ((float4*)sA)[t] = r[0];                  // matrix 0 as rows
    transpose_store(r[1], sBt[1], t);         // matrix 1 transposed
    __syncthreads();

    float acc0 = 0.f, acc1 = 0.f, acc2 = 0.f, acc3 = 0.f;

    #pragma unroll
    for (int s = 1; s < 8; ++s) {
        const float* Bt = sBt[s & 1];
        acc0 = acc1 = acc2 = acc3 = 0.f;

        #pragma unroll
        for (int l4 = 0; l4 < 8; ++l4) {
            const float4 a0 = *(const float4*)(sA + (4 * w + 0) * 32 + 4 * l4);
            const float4 a1 = *(const float4*)(sA + (4 * w + 1) * 32 + 4 * l4);
            const float4 a2 = *(const float4*)(sA + (4 * w + 2) * 32 + 4 * l4);
            const float4 a3 = *(const float4*)(sA + (4 * w + 3) * 32 + 4 * l4);
            const float b0 = Bt[lane * 33 + 4 * l4 + 0];
            const float b1 = Bt[lane * 33 + 4 * l4 + 1];
            const float b2 = Bt[lane * 33 + 4 * l4 + 2];
            const float b3 = Bt[lane * 33 + 4 * l4 + 3];

            acc0 = fmaf(a0.x, b0, acc0); acc0 = fmaf(a0.y, b1, acc0);
            acc0 = fmaf(a0.z, b2, acc0); acc0 = fmaf(a0.w, b3, acc0);
            acc1 = fmaf(a1.x, b0, acc1); acc1 = fmaf(a1.y, b1, acc1);
            acc1 = fmaf(a1.z, b2, acc1); acc1 = fmaf(a1.w, b3, acc1);
            acc2 = fmaf(a2.x, b0, acc2); acc2 = fmaf(a2.y, b1, acc2);
            acc2 = fmaf(a2.z, b2, acc2); acc2 = fmaf(a2.w, b3, acc2);
            acc3 = fmaf(a3.x, b0, acc3); acc3 = fmaf(a3.y, b1, acc3);
            acc3 = fmaf(a3.z, b2, acc3); acc3 = fmaf(a3.w, b3, acc3);
        }
        __syncthreads();
        if (s < 7) {
            sA[(4 * w + 0) * 32 + lane] = acc0;
            sA[(4 * w + 1) * 32 + lane] = acc1;
            sA[(4 * w + 2) * 32 + lane] = acc2;
            sA[(4 * w + 3) * 32 + lane] = acc3;
            transpose_store(r[s + 1], sBt[(s + 1) & 1], t);
            __syncthreads();
        }
    }

    float* d = dst + (size_t)blockIdx.x * (BOND * BOND);
    d[(4 * w + 0) * 32 + lane] = acc0;
    d[(4 * w + 1) * 32 + lane] = acc1;
    d[(4 * w + 2) * 32 + lane] = acc2;
    d[(4 * w + 3) * 32 + lane] = acc3;
}

// ---------------------------------------------------------------------------
// Fused final kernel: 128 blocks x 1024 threads, 32 batch rows per block
// (one warp per row). Stages the 16 P2 matrices (64KB smem), computes per-row
// scalar products while warp 0 runs the 16-step vector chain, 512 threads do
// w = v @ proj once per block, then all warps write out = s*w + bias.
// ---------------------------------------------------------------------------
#define SMEM_FLOATS (NP2 * 1024 + ODIM + BOND)

__global__ __launch_bounds__(1024) void mps_output_fused_kernel(
        const float* __restrict__ inputs,
        const float* __restrict__ proj,
        const float* __restrict__ bias,
        float* __restrict__ out) {
    extern __shared__ float sP[];
    float* sw = sP + NP2 * 1024;
    float* sv = sw + ODIM;

    const int tid  = threadIdx.x;
    const int wid  = tid >> 5;
    const int lane = tid & 31;
    const int b    = blockIdx.x * 32 + wid;

    // input row loads (deep MLP, independent of staging)
    const float4* row = (const float4*)(inputs + (size_t)b * IDIM);
    float4 r[8];
    #pragma unroll
    for (int i = 0; i < 8; ++i) r[i] = row[lane + 32 * i];

    // stage P2: 1024 threads * 4 float4 = 64KB
    {
        const float4* g4 = (const float4*)g_P2;
        float4*       s4 = (float4*)sP;
        #pragma unroll
        for (int i = 0; i < 4; ++i) s4[tid + 1024 * i] = g4[tid + 1024 * i];
    }

    // per-row product
    float p0 = (r[0].x * r[0].y) * (r[0].z * r[0].w);
    float p1 = (r[1].x * r[1].y) * (r[1].z * r[1].w);
    float p2 = (r[2].x * r[2].y) * (r[2].z * r[2].w);
    float p3 = (r[3].x * r[3].y) * (r[3].z * r[3].w);
    float p4 = (r[4].x * r[4].y) * (r[4].z * r[4].w);
    float p5 = (r[5].x * r[5].y) * (r[5].z * r[5].w);
    float p6 = (r[6].x * r[6].y) * (r[6].z * r[6].w);
    float p7 = (r[7].x * r[7].y) * (r[7].z * r[7].w);
    float p  = ((p0 * p1) * (p2 * p3)) * ((p4 * p5) * (p6 * p7));
    #pragma unroll
    for (int off = 16; off; off >>= 1)
        p *= __shfl_xor_sync(0xffffffffu, p, off);

    __syncthreads();           // staging visible

    // warp 0: 16-step vector chain from smem (broadcast LDS)
    if (wid == 0) {
        float v = 1.0f;
        #pragma unroll
        for (int c = 0; c < NP2; ++c) {
            const float* P = sP + c * 1024;
            float a0 = 0.f, a1 = 0.f, a2 = 0.f, a3 = 0.f;
            #pragma unroll
            for (int j = 0; j < 8; ++j) {
                a0 = fmaf(__shfl_sync(0xffffffffu, v, j),      P[j * 32 + lane],        a0);
                a1 = fmaf(__shfl_sync(0xffffffffu, v, j + 8),  P[(j + 8) * 32 + lane],  a1);
                a2 = fmaf(__shfl_sync(0xffffffffu, v, j + 16), P[(j + 16) * 32 + lane], a2);
                a3 = fmaf(__shfl_sync(0xffffffffu, v, j + 24), P[(j + 24) * 32 + lane], a3);
            }
            v = (a0 + a1) + (a2 + a3);
        }
        sv[lane] = v;
    }
    __syncthreads();           // sv ready

    // w = v @ projection (512 threads; 32 outstanding LDGs hide latency)
    if (tid < ODIM) {
        float a0 = 0.f, a1 = 0.f, a2 = 0.f, a3 = 0.f;
        #pragma unroll
        for (int j = 0; j < 8; ++j) {
            a0 = fmaf(sv[j],      proj[(j)      * ODIM + tid], a0);
            a1 = fmaf(sv[j + 8],  proj[(j + 8)  * ODIM + tid], a1);
            a2 = fmaf(sv[j + 16], proj[(j + 16) * ODIM + tid], a2);
            a3 = fmaf(sv[j + 24], proj[(j + 24) * ODIM + tid], a3);
        }
        sw[tid] = (a0 + a1) + (a2 + a3);
    }
    __syncthreads();           // sw ready

    // write out[b,:] = p * sw + bias
    const float4* w4 = (const float4*)sw;
    const float4* b4 = (const float4*)bias;
    float4*       o4 = (float4*)(out + (size_t)b * ODIM);
    #pragma unroll
    for (int i = 0; i < 4; ++i) {
        const float4 wv = w4[lane + 32 * i];
        const float4 bv = b4[lane + 32 * i];
        float4 ov;
        ov.x = fmaf(p, wv.x, bv.x);
        ov.y = fmaf(p, wv.y, bv.y);
        ov.z = fmaf(p, wv.z, bv.z);
        ov.w = fmaf(p, wv.w, bv.w);
        o4[lane + 32 * i] = ov;
    }
}

// ---------------------------------------------------------------------------
extern "C" void kernel_launch(void* const* d_in, const int* in_sizes, int n_in,
                              void* d_out, int out_size) {
    const float* inputs = (const float*)d_in[0];
    const float* cores  = (const float*)d_in[1];
    const float* proj   = (const float*)d_in[2];
    const float* bias   = (const float*)d_in[3];
    float* out = (float*)d_out;

    float* p1; cudaGetSymbolAddress((void**)&p1, g_P1);
    float* p2; cudaGetSymbolAddress((void**)&p2, g_P2);

    cudaFuncSetAttribute(mps_output_fused_kernel,
                         cudaFuncAttributeMaxDynamicSharedMemorySize,
                         SMEM_FLOATS * (int)sizeof(float));

    mps_prod8_kernel<<<NP1, 256>>>(cores, p1);   // 1024 -> 128
    mps_prod8_kernel<<<NP2, 256>>>(p1, p2);      // 128  -> 16
    mps_output_fused_kernel<<<BATCH / 32, 1024, SMEM_FLOATS * sizeof(float)>>>(
        inputs, proj, bias, out);
}